// round 5
// baseline (speedup 1.0000x reference)
#include <cuda_runtime.h>
#include <math.h>

// Problem constants
#define Bsz    8
#define Tlen   1024
#define EMB    1024
#define NHEADS 16
#define HD     64
#define CHUNK  64

#define MTOT (Bsz * Tlen)          // 8192 rows

// ---------------------------------------------------------------------------
// Scratch (device globals — allocation-free per harness rules)
// ---------------------------------------------------------------------------
__device__ float g_q[MTOT * EMB];
__device__ float g_k[MTOT * EMB];
__device__ float g_v[MTOT * EMB];
__device__ float g_attn[MTOT * EMB];

// ---------------------------------------------------------------------------
// GEMM: C[M,N] = A[M,K] * B[N,K]^T + bias[N]      (torch Linear semantics)
// M=8192, N=K=1024. BM=BN=64, BK=16, 256 threads, 4x4 micro tile.
// ---------------------------------------------------------------------------
#define BM 64
#define BN 64
#define BK 16

__global__ __launch_bounds__(256)
void gemm_nt_bias(const float* __restrict__ A, const float* __restrict__ B,
                  const float* __restrict__ bias, float* __restrict__ C,
                  int M, int N, int K)
{
    __shared__ float As[BK][BM + 4];   // transposed: As[k][m]
    __shared__ float Bs[BK][BN + 4];   // transposed: Bs[k][n]

    const int tid = threadIdx.x;
    const int tx = tid & 15;           // 0..15  -> n micro
    const int ty = tid >> 4;           // 0..15  -> m micro
    const int mBase = blockIdx.y * BM;
    const int nBase = blockIdx.x * BN;

    const int lrow = tid >> 2;         // 0..63
    const int lk   = (tid & 3) * 4;    // 0,4,8,12

    const float* Ag = A + (size_t)(mBase + lrow) * K + lk;
    const float* Bg = B + (size_t)(nBase + lrow) * K + lk;

    float acc[4][4];
#pragma unroll
    for (int i = 0; i < 4; i++)
#pragma unroll
        for (int j = 0; j < 4; j++) acc[i][j] = 0.f;

    for (int k0 = 0; k0 < K; k0 += BK) {
        float4 a = *(const float4*)(Ag + k0);
        float4 b = *(const float4*)(Bg + k0);
        As[lk + 0][lrow] = a.x; As[lk + 1][lrow] = a.y;
        As[lk + 2][lrow] = a.z; As[lk + 3][lrow] = a.w;
        Bs[lk + 0][lrow] = b.x; Bs[lk + 1][lrow] = b.y;
        Bs[lk + 2][lrow] = b.z; Bs[lk + 3][lrow] = b.w;
        __syncthreads();

#pragma unroll
        for (int kk = 0; kk < BK; kk++) {
            float4 av = *(const float4*)(&As[kk][ty * 4]);
            float4 bv = *(const float4*)(&Bs[kk][tx * 4]);
            float am[4] = {av.x, av.y, av.z, av.w};
            float bn[4] = {bv.x, bv.y, bv.z, bv.w};
#pragma unroll
            for (int i = 0; i < 4; i++)
#pragma unroll
                for (int j = 0; j < 4; j++)
                    acc[i][j] = fmaf(am[i], bn[j], acc[i][j]);
        }
        __syncthreads();
    }

    const int col = nBase + tx * 4;
    float4 bv = *(const float4*)(bias + col);
#pragma unroll
    for (int i = 0; i < 4; i++) {
        int row = mBase + ty * 4 + i;
        float4 o;
        o.x = acc[i][0] + bv.x;
        o.y = acc[i][1] + bv.y;
        o.z = acc[i][2] + bv.z;
        o.w = acc[i][3] + bv.w;
        *(float4*)(C + (size_t)row * N + col) = o;
    }
}

// ---------------------------------------------------------------------------
// Fused attention, flash-style.
// Mask: key j masked for query i iff j>i AND same CHUNK(=64) block
//       => only the diagonal 64x64 key tile is (triangularly) masked.
// Block: (q-tile, head, batch). 256 threads = 64 query rows x 4 subs.
// Each sub owns 16 keys during score compute and 16 output dims during PV.
// ---------------------------------------------------------------------------
#define QT 64
#define KT 64
#define LDP 68   // padded row length (floats), float4-aligned, bank-friendly

__global__ __launch_bounds__(256)
void attn_kernel(const float* __restrict__ Q, const float* __restrict__ K,
                 const float* __restrict__ V, const float* __restrict__ scale_p,
                 float* __restrict__ O)
{
    extern __shared__ float smem[];
    float (*Qs)[LDP] = (float(*)[LDP])(smem);
    float (*Ks)[LDP] = (float(*)[LDP])(smem + QT * LDP);
    float (*Vs)[LDP] = (float(*)[LDP])(smem + 2 * QT * LDP);
    float (*Ps)[LDP] = (float(*)[LDP])(smem + 3 * QT * LDP);

    const int tid = threadIdx.x;
    const int qi  = tid >> 2;      // 0..63 query row in tile
    const int sub = tid & 3;       // 0..3
    const int qt = blockIdx.x, h = blockIdx.y, b = blockIdx.z;
    const float scale = scale_p[0];

    // Load Q tile (each thread: 16 floats = quarter of one row)
    {
        const int r = tid >> 2, c = (tid & 3) * 16;
        const float* Qb = Q + ((size_t)b * Tlen + qt * QT + r) * EMB + h * HD + c;
#pragma unroll
        for (int j = 0; j < 4; j++)
            *(float4*)&Qs[r][c + 4 * j] = *(const float4*)(Qb + 4 * j);
    }

    float m = -INFINITY, l = 0.f;
    float acc[16];
#pragma unroll
    for (int i = 0; i < 16; i++) acc[i] = 0.f;

    const int kbase = sub * 16;

    for (int kt = 0; kt < Tlen / KT; kt++) {
        __syncthreads();   // protects Ks/Vs/Ps reuse across iterations (and Qs first iter)
        {
            const int r = tid >> 2, c = (tid & 3) * 16;
            const float* Kb = K + ((size_t)b * Tlen + kt * KT + r) * EMB + h * HD + c;
            const float* Vb = V + ((size_t)b * Tlen + kt * KT + r) * EMB + h * HD + c;
#pragma unroll
            for (int j = 0; j < 4; j++) {
                *(float4*)&Ks[r][c + 4 * j] = *(const float4*)(Kb + 4 * j);
                *(float4*)&Vs[r][c + 4 * j] = *(const float4*)(Vb + 4 * j);
            }
        }
        __syncthreads();

        // Scores: this thread's 16 keys vs its query row
        float s[16];
#pragma unroll
        for (int j = 0; j < 16; j++) {
            float a0 = 0.f, a1 = 0.f, a2 = 0.f, a3 = 0.f;
#pragma unroll
            for (int d = 0; d < HD; d += 4) {
                float4 qv = *(const float4*)&Qs[qi][d];
                float4 kv = *(const float4*)&Ks[kbase + j][d];
                a0 = fmaf(qv.x, kv.x, a0);
                a1 = fmaf(qv.y, kv.y, a1);
                a2 = fmaf(qv.z, kv.z, a2);
                a3 = fmaf(qv.w, kv.w, a3);
            }
            s[j] = ((a0 + a1) + (a2 + a3)) * scale;
        }
        if (kt == qt) {
#pragma unroll
            for (int j = 0; j < 16; j++)
                if (kbase + j > qi) s[j] = -INFINITY;
        }

        // Online softmax (combine across the 4 subs of this query row)
        float tmax = s[0];
#pragma unroll
        for (int j = 1; j < 16; j++) tmax = fmaxf(tmax, s[j]);
        tmax = fmaxf(tmax, __shfl_xor_sync(0xffffffffu, tmax, 1));
        tmax = fmaxf(tmax, __shfl_xor_sync(0xffffffffu, tmax, 2));
        float mnew = fmaxf(m, tmax);
        float corr = __expf(m - mnew);   // 0 when m == -inf

        float tsum = 0.f;
#pragma unroll
        for (int j = 0; j < 16; j++) {
            float p = __expf(s[j] - mnew);
            Ps[qi][kbase + j] = p;
            tsum += p;
        }
        tsum += __shfl_xor_sync(0xffffffffu, tsum, 1);
        tsum += __shfl_xor_sync(0xffffffffu, tsum, 2);
        l = l * corr + tsum;
        m = mnew;
#pragma unroll
        for (int i = 0; i < 16; i++) acc[i] *= corr;

        __syncthreads();   // Ps visible to all subs of this row

        // PV: this thread accumulates 16 output dims over all 64 keys
#pragma unroll 4
        for (int kn = 0; kn < KT; kn++) {
            float p = Ps[qi][kn];
#pragma unroll
            for (int i = 0; i < 16; i += 4) {
                float4 vv = *(const float4*)&Vs[kn][sub * 16 + i];
                acc[i + 0] = fmaf(p, vv.x, acc[i + 0]);
                acc[i + 1] = fmaf(p, vv.y, acc[i + 1]);
                acc[i + 2] = fmaf(p, vv.z, acc[i + 2]);
                acc[i + 3] = fmaf(p, vv.w, acc[i + 3]);
            }
        }
    }

    const float linv = 1.f / l;
    float* Ob = O + ((size_t)b * Tlen + qt * QT + qi) * EMB + h * HD + sub * 16;
#pragma unroll
    for (int i = 0; i < 16; i += 4) {
        float4 o = make_float4(acc[i] * linv, acc[i + 1] * linv,
                               acc[i + 2] * linv, acc[i + 3] * linv);
        *(float4*)(Ob + i) = o;
    }
}

// ---------------------------------------------------------------------------
// Launch
// ---------------------------------------------------------------------------
extern "C" void kernel_launch(void* const* d_in, const int* in_sizes, int n_in,
                              void* d_out, int out_size)
{
    const float* x     = (const float*)d_in[0];
    const float* Wq    = (const float*)d_in[1];
    const float* bq    = (const float*)d_in[2];
    const float* Wk    = (const float*)d_in[3];
    const float* bk    = (const float*)d_in[4];
    const float* Wv    = (const float*)d_in[5];
    const float* bv    = (const float*)d_in[6];
    const float* Wo    = (const float*)d_in[7];
    const float* bo    = (const float*)d_in[8];
    const float* ascl  = (const float*)d_in[9];
    float* out = (float*)d_out;

    float *q, *k, *v, *attn;
    cudaGetSymbolAddress((void**)&q,    g_q);
    cudaGetSymbolAddress((void**)&k,    g_k);
    cudaGetSymbolAddress((void**)&v,    g_v);
    cudaGetSymbolAddress((void**)&attn, g_attn);

    const int M = MTOT, N = EMB, K = EMB;
    dim3 ggrid(N / BN, M / BM);   // (16, 128)
    dim3 gblk(256);

    gemm_nt_bias<<<ggrid, gblk>>>(x, Wq, bq, q, M, N, K);
    gemm_nt_bias<<<ggrid, gblk>>>(x, Wk, bk, k, M, N, K);
    gemm_nt_bias<<<ggrid, gblk>>>(x, Wv, bv, v, M, N, K);

    const int smem_bytes = 4 * QT * LDP * (int)sizeof(float);   // 69,632 B
    static int attr_set = 0;
    cudaFuncSetAttribute(attn_kernel,
                         cudaFuncAttributeMaxDynamicSharedMemorySize, smem_bytes);
    (void)attr_set;

    dim3 agrid(Tlen / QT, NHEADS, Bsz);  // (16, 16, 8)
    attn_kernel<<<agrid, 256, smem_bytes>>>(q, k, v, ascl, attn);

    gemm_nt_bias<<<ggrid, gblk>>>(attn, Wo, bo, out, M, N, K);
}

// round 6
// speedup vs baseline: 2.7307x; 2.7307x over previous
#include <cuda_runtime.h>
#include <math.h>

// Problem constants
#define Bsz    8
#define Tlen   1024
#define EMB    1024
#define NHEADS 16
#define HD     64
#define CHUNK  64

#define MTOT (Bsz * Tlen)          // 8192 rows

// ---------------------------------------------------------------------------
// Scratch (device globals — allocation-free per harness rules)
// ---------------------------------------------------------------------------
__device__ float g_q[MTOT * EMB];
__device__ float g_k[MTOT * EMB];
__device__ float g_v[MTOT * EMB];
__device__ float g_attn[MTOT * EMB];

// ---------------------------------------------------------------------------
// GEMM: C[M,N] = A[M,K] * B[N,K]^T + bias[N]      (torch Linear semantics)
// BM=BN=128, BK=16, 256 threads, 8x8 micro tile (2x2 blocks of 4x4 at +0/+64).
// 64 FMA per 4 LDS.128 in the inner loop -> FMA-bound.
// ---------------------------------------------------------------------------
#define BM 128
#define BN 128
#define BK 16
#define LDA (BM + 4)
#define LDB (BN + 4)

__global__ __launch_bounds__(256)
void gemm_nt_bias(const float* __restrict__ A, const float* __restrict__ B,
                  const float* __restrict__ bias, float* __restrict__ C,
                  int M, int N, int K)
{
    __shared__ float As[BK][LDA];   // transposed: As[k][m]
    __shared__ float Bs[BK][LDB];   // transposed: Bs[k][n]

    const int tid = threadIdx.x;
    const int tx = tid & 15;           // 0..15  -> n micro
    const int ty = tid >> 4;           // 0..15  -> m micro
    const int mBase = blockIdx.y * BM;
    const int nBase = blockIdx.x * BN;

    // loader mapping: 256 threads cover 128 rows x 16 k-cols (2 float4 each)
    const int lr = tid >> 1;           // 0..127
    const int lc = (tid & 1) * 8;      // 0 or 8

    const float* Ag = A + (size_t)(mBase + lr) * K + lc;
    const float* Bg = B + (size_t)(nBase + lr) * K + lc;

    float acc[8][8];
#pragma unroll
    for (int i = 0; i < 8; i++)
#pragma unroll
        for (int j = 0; j < 8; j++) acc[i][j] = 0.f;

    for (int k0 = 0; k0 < K; k0 += BK) {
        float4 a0 = *(const float4*)(Ag + k0);
        float4 a1 = *(const float4*)(Ag + k0 + 4);
        float4 b0 = *(const float4*)(Bg + k0);
        float4 b1 = *(const float4*)(Bg + k0 + 4);

        As[lc + 0][lr] = a0.x; As[lc + 1][lr] = a0.y;
        As[lc + 2][lr] = a0.z; As[lc + 3][lr] = a0.w;
        As[lc + 4][lr] = a1.x; As[lc + 5][lr] = a1.y;
        As[lc + 6][lr] = a1.z; As[lc + 7][lr] = a1.w;

        Bs[lc + 0][lr] = b0.x; Bs[lc + 1][lr] = b0.y;
        Bs[lc + 2][lr] = b0.z; Bs[lc + 3][lr] = b0.w;
        Bs[lc + 4][lr] = b1.x; Bs[lc + 5][lr] = b1.y;
        Bs[lc + 6][lr] = b1.z; Bs[lc + 7][lr] = b1.w;
        __syncthreads();

#pragma unroll
        for (int kk = 0; kk < BK; kk++) {
            float4 aL = *(const float4*)(&As[kk][ty * 4]);
            float4 aH = *(const float4*)(&As[kk][ty * 4 + 64]);
            float4 bL = *(const float4*)(&Bs[kk][tx * 4]);
            float4 bH = *(const float4*)(&Bs[kk][tx * 4 + 64]);
            float am[8] = {aL.x, aL.y, aL.z, aL.w, aH.x, aH.y, aH.z, aH.w};
            float bn[8] = {bL.x, bL.y, bL.z, bL.w, bH.x, bH.y, bH.z, bH.w};
#pragma unroll
            for (int i = 0; i < 8; i++)
#pragma unroll
                for (int j = 0; j < 8; j++)
                    acc[i][j] = fmaf(am[i], bn[j], acc[i][j]);
        }
        __syncthreads();
    }

    const int colL = nBase + tx * 4;
    const int colH = colL + 64;
    float4 bvL = *(const float4*)(bias + colL);
    float4 bvH = *(const float4*)(bias + colH);

#pragma unroll
    for (int hm = 0; hm < 2; hm++) {
#pragma unroll
        for (int i = 0; i < 4; i++) {
            int row = mBase + ty * 4 + i + hm * 64;
            int ii = hm * 4 + i;
            float4 oL, oH;
            oL.x = acc[ii][0] + bvL.x; oL.y = acc[ii][1] + bvL.y;
            oL.z = acc[ii][2] + bvL.z; oL.w = acc[ii][3] + bvL.w;
            oH.x = acc[ii][4] + bvH.x; oH.y = acc[ii][5] + bvH.y;
            oH.z = acc[ii][6] + bvH.z; oH.w = acc[ii][7] + bvH.w;
            *(float4*)(C + (size_t)row * N + colL) = oL;
            *(float4*)(C + (size_t)row * N + colH) = oH;
        }
    }
}

// ---------------------------------------------------------------------------
// Fused attention, flash-style, register-blocked.
// Mask: only the diagonal 64x64 key tile is (triangularly) masked.
// Block = (q-tile 64, head, batch). 256 threads as 16x16; each thread owns a
// 4x4 tile of S (q rows ty*4.., key cols tx*4..) and the SAME 4 q-rows x
// 4 out-dims of O. Row softmax stats live in registers, reduced via shfl
// within the 16-lane tx group.
// ---------------------------------------------------------------------------
#define QT 64
#define LDP 68   // padded row length (floats), float4-aligned

__global__ __launch_bounds__(256)
void attn_kernel(const float* __restrict__ Q, const float* __restrict__ K,
                 const float* __restrict__ V, const float* __restrict__ scale_p,
                 float* __restrict__ O)
{
    extern __shared__ float smem[];
    float (*Qs)[LDP] = (float(*)[LDP])(smem);                 // [d][q]  (transposed)
    float (*Ks)[LDP] = (float(*)[LDP])(smem + QT * LDP);      // [d][k]  (transposed)
    float (*Vs)[LDP] = (float(*)[LDP])(smem + 2 * QT * LDP);  // [k][d]  (natural)
    float (*Ps)[LDP] = (float(*)[LDP])(smem + 3 * QT * LDP);  // [q][k]  (natural)

    const int tid = threadIdx.x;
    const int tx = tid & 15;
    const int ty = tid >> 4;
    const int qt = blockIdx.x, h = blockIdx.y, b = blockIdx.z;
    const float scale = scale_p[0];

    // loader mapping: r = row 0..63, c = 16-float column chunk
    const int r = tid >> 2;
    const int c = (tid & 3) * 16;

    // Load Q tile transposed, scale folded in
    {
        const float* Qb = Q + ((size_t)b * Tlen + qt * QT + r) * EMB + h * HD + c;
#pragma unroll
        for (int j = 0; j < 4; j++) {
            float4 q4 = *(const float4*)(Qb + 4 * j);
            Qs[c + 4 * j + 0][r] = q4.x * scale;
            Qs[c + 4 * j + 1][r] = q4.y * scale;
            Qs[c + 4 * j + 2][r] = q4.z * scale;
            Qs[c + 4 * j + 3][r] = q4.w * scale;
        }
    }

    float m[4], l[4], o[4][4];
#pragma unroll
    for (int i = 0; i < 4; i++) {
        m[i] = -INFINITY; l[i] = 0.f;
#pragma unroll
        for (int j = 0; j < 4; j++) o[i][j] = 0.f;
    }

    for (int kt = 0; kt < Tlen / QT; kt++) {
        __syncthreads();   // protect Ks/Vs/Ps reuse (and Qs on first iter)
        {
            const float* Kb = K + ((size_t)b * Tlen + kt * QT + r) * EMB + h * HD + c;
            const float* Vb = V + ((size_t)b * Tlen + kt * QT + r) * EMB + h * HD + c;
#pragma unroll
            for (int j = 0; j < 4; j++) {
                float4 k4 = *(const float4*)(Kb + 4 * j);
                Ks[c + 4 * j + 0][r] = k4.x;
                Ks[c + 4 * j + 1][r] = k4.y;
                Ks[c + 4 * j + 2][r] = k4.z;
                Ks[c + 4 * j + 3][r] = k4.w;
                *(float4*)&Vs[r][c + 4 * j] = *(const float4*)(Vb + 4 * j);
            }
        }
        __syncthreads();

        // ---- S = (Q*scale) . K^T : 4x4 register tile ----
        float s[4][4];
#pragma unroll
        for (int i = 0; i < 4; i++)
#pragma unroll
            for (int j = 0; j < 4; j++) s[i][j] = 0.f;

#pragma unroll 8
        for (int d = 0; d < HD; d++) {
            float4 qv = *(const float4*)&Qs[d][ty * 4];
            float4 kv = *(const float4*)&Ks[d][tx * 4];
            float qa[4] = {qv.x, qv.y, qv.z, qv.w};
            float kb[4] = {kv.x, kv.y, kv.z, kv.w};
#pragma unroll
            for (int i = 0; i < 4; i++)
#pragma unroll
                for (int j = 0; j < 4; j++)
                    s[i][j] = fmaf(qa[i], kb[j], s[i][j]);
        }

        if (kt == qt) {
#pragma unroll
            for (int i = 0; i < 4; i++)
#pragma unroll
                for (int j = 0; j < 4; j++)
                    if (tx * 4 + j > ty * 4 + i) s[i][j] = -INFINITY;
        }

        // ---- online softmax: per-row stats reduced over the 16 tx lanes ----
#pragma unroll
        for (int i = 0; i < 4; i++) {
            float tm = fmaxf(fmaxf(s[i][0], s[i][1]), fmaxf(s[i][2], s[i][3]));
            tm = fmaxf(tm, __shfl_xor_sync(0xffffffffu, tm, 1));
            tm = fmaxf(tm, __shfl_xor_sync(0xffffffffu, tm, 2));
            tm = fmaxf(tm, __shfl_xor_sync(0xffffffffu, tm, 4));
            tm = fmaxf(tm, __shfl_xor_sync(0xffffffffu, tm, 8));
            float mnew = fmaxf(m[i], tm);
            float corr = __expf(m[i] - mnew);   // 0 when m == -inf

            float4 p;
            p.x = __expf(s[i][0] - mnew);
            p.y = __expf(s[i][1] - mnew);
            p.z = __expf(s[i][2] - mnew);
            p.w = __expf(s[i][3] - mnew);
            float ts = (p.x + p.y) + (p.z + p.w);
            ts += __shfl_xor_sync(0xffffffffu, ts, 1);
            ts += __shfl_xor_sync(0xffffffffu, ts, 2);
            ts += __shfl_xor_sync(0xffffffffu, ts, 4);
            ts += __shfl_xor_sync(0xffffffffu, ts, 8);
            l[i] = l[i] * corr + ts;
            m[i] = mnew;
#pragma unroll
            for (int j = 0; j < 4; j++) o[i][j] *= corr;
            *(float4*)&Ps[ty * 4 + i][tx * 4] = p;
        }
        __syncthreads();   // Ps complete before PV

        // ---- O += P . V : 4x4 register tile, kk unrolled by 4 ----
#pragma unroll 4
        for (int kk = 0; kk < QT; kk += 4) {
            float4 vv0 = *(const float4*)&Vs[kk + 0][tx * 4];
            float4 vv1 = *(const float4*)&Vs[kk + 1][tx * 4];
            float4 vv2 = *(const float4*)&Vs[kk + 2][tx * 4];
            float4 vv3 = *(const float4*)&Vs[kk + 3][tx * 4];
#pragma unroll
            for (int i = 0; i < 4; i++) {
                float4 pr = *(const float4*)&Ps[ty * 4 + i][kk];
                o[i][0] = fmaf(pr.x, vv0.x, o[i][0]);
                o[i][1] = fmaf(pr.x, vv0.y, o[i][1]);
                o[i][2] = fmaf(pr.x, vv0.z, o[i][2]);
                o[i][3] = fmaf(pr.x, vv0.w, o[i][3]);
                o[i][0] = fmaf(pr.y, vv1.x, o[i][0]);
                o[i][1] = fmaf(pr.y, vv1.y, o[i][1]);
                o[i][2] = fmaf(pr.y, vv1.z, o[i][2]);
                o[i][3] = fmaf(pr.y, vv1.w, o[i][3]);
                o[i][0] = fmaf(pr.z, vv2.x, o[i][0]);
                o[i][1] = fmaf(pr.z, vv2.y, o[i][1]);
                o[i][2] = fmaf(pr.z, vv2.z, o[i][2]);
                o[i][3] = fmaf(pr.z, vv2.w, o[i][3]);
                o[i][0] = fmaf(pr.w, vv3.x, o[i][0]);
                o[i][1] = fmaf(pr.w, vv3.y, o[i][1]);
                o[i][2] = fmaf(pr.w, vv3.z, o[i][2]);
                o[i][3] = fmaf(pr.w, vv3.w, o[i][3]);
            }
        }
    }

    // ---- finalize + store ----
#pragma unroll
    for (int i = 0; i < 4; i++) {
        float inv = 1.f / l[i];
        float* Ob = O + ((size_t)b * Tlen + qt * QT + ty * 4 + i) * EMB
                      + h * HD + tx * 4;
        float4 ov = make_float4(o[i][0] * inv, o[i][1] * inv,
                                o[i][2] * inv, o[i][3] * inv);
        *(float4*)Ob = ov;
    }
}

// ---------------------------------------------------------------------------
// Launch
// ---------------------------------------------------------------------------
extern "C" void kernel_launch(void* const* d_in, const int* in_sizes, int n_in,
                              void* d_out, int out_size)
{
    const float* x     = (const float*)d_in[0];
    const float* Wq    = (const float*)d_in[1];
    const float* bq    = (const float*)d_in[2];
    const float* Wk    = (const float*)d_in[3];
    const float* bk    = (const float*)d_in[4];
    const float* Wv    = (const float*)d_in[5];
    const float* bv    = (const float*)d_in[6];
    const float* Wo    = (const float*)d_in[7];
    const float* bo    = (const float*)d_in[8];
    const float* ascl  = (const float*)d_in[9];
    float* out = (float*)d_out;

    float *q, *k, *v, *attn;
    cudaGetSymbolAddress((void**)&q,    g_q);
    cudaGetSymbolAddress((void**)&k,    g_k);
    cudaGetSymbolAddress((void**)&v,    g_v);
    cudaGetSymbolAddress((void**)&attn, g_attn);

    const int M = MTOT, N = EMB, K = EMB;
    dim3 ggrid(N / BN, M / BM);   // (8, 64)
    dim3 gblk(256);

    gemm_nt_bias<<<ggrid, gblk>>>(x, Wq, bq, q, M, N, K);
    gemm_nt_bias<<<ggrid, gblk>>>(x, Wk, bk, k, M, N, K);
    gemm_nt_bias<<<ggrid, gblk>>>(x, Wv, bv, v, M, N, K);

    const int smem_bytes = 4 * QT * LDP * (int)sizeof(float);   // 69,632 B
    cudaFuncSetAttribute(attn_kernel,
                         cudaFuncAttributeMaxDynamicSharedMemorySize, smem_bytes);

    dim3 agrid(Tlen / QT, NHEADS, Bsz);  // (16, 16, 8)
    attn_kernel<<<agrid, 256, smem_bytes>>>(q, k, v, ascl, attn);

    gemm_nt_bias<<<ggrid, gblk>>>(attn, Wo, bo, out, M, N, K);
}

// round 8
// speedup vs baseline: 2.8089x; 1.0286x over previous
#include <cuda_runtime.h>
#include <math.h>

// Problem constants
#define Bsz    8
#define Tlen   1024
#define EMB    1024
#define NHEADS 16
#define HD     64
#define CHUNK  64

#define MTOT (Bsz * Tlen)          // 8192 rows

// ---------------------------------------------------------------------------
// Scratch (device globals — allocation-free per harness rules)
// ---------------------------------------------------------------------------
__device__ float g_q[MTOT * EMB];
__device__ float g_k[MTOT * EMB];
__device__ float g_v[MTOT * EMB];
__device__ float g_attn[MTOT * EMB];

// ---------------------------------------------------------------------------
// GEMM: C[M,N] = A[M,K] * B[N,K]^T + bias[N]      (torch Linear semantics)
// BM=BN=128, BK=16, 256 threads, 8x8 micro tile, double-buffered smem with
// register prefetch of the next global tile. One __syncthreads per k-iter.
// ---------------------------------------------------------------------------
#define BM 128
#define BN 128
#define BK 16
#define LDA (BM + 4)
#define LDB (BN + 4)

__global__ __launch_bounds__(256)
void gemm_nt_bias(const float* __restrict__ A, const float* __restrict__ B,
                  const float* __restrict__ bias, float* __restrict__ C,
                  int M, int N, int K)
{
    __shared__ float As[2][BK][LDA];   // transposed: As[buf][k][m]
    __shared__ float Bs[2][BK][LDB];   // transposed: Bs[buf][k][n]

    const int tid = threadIdx.x;
    const int tx = tid & 15;           // n micro
    const int ty = tid >> 4;           // m micro
    const int mBase = blockIdx.y * BM;
    const int nBase = blockIdx.x * BN;

    const int lr = tid >> 1;           // 0..127
    const int lc = (tid & 1) * 8;      // 0 or 8

    const float* Ag = A + (size_t)(mBase + lr) * K + lc;
    const float* Bg = B + (size_t)(nBase + lr) * K + lc;

    float acc[8][8];
#pragma unroll
    for (int i = 0; i < 8; i++)
#pragma unroll
        for (int j = 0; j < 8; j++) acc[i][j] = 0.f;

    // preload first tile into buffer 0
    {
        float4 a0 = *(const float4*)(Ag);
        float4 a1 = *(const float4*)(Ag + 4);
        float4 b0 = *(const float4*)(Bg);
        float4 b1 = *(const float4*)(Bg + 4);
        As[0][lc + 0][lr] = a0.x; As[0][lc + 1][lr] = a0.y;
        As[0][lc + 2][lr] = a0.z; As[0][lc + 3][lr] = a0.w;
        As[0][lc + 4][lr] = a1.x; As[0][lc + 5][lr] = a1.y;
        As[0][lc + 6][lr] = a1.z; As[0][lc + 7][lr] = a1.w;
        Bs[0][lc + 0][lr] = b0.x; Bs[0][lc + 1][lr] = b0.y;
        Bs[0][lc + 2][lr] = b0.z; Bs[0][lc + 3][lr] = b0.w;
        Bs[0][lc + 4][lr] = b1.x; Bs[0][lc + 5][lr] = b1.y;
        Bs[0][lc + 6][lr] = b1.z; Bs[0][lc + 7][lr] = b1.w;
    }
    __syncthreads();

    int buf = 0;
    for (int k0 = 0; k0 < K; k0 += BK) {
        float4 pa0, pa1, pb0, pb1;
        const bool more = (k0 + BK) < K;
        if (more) {
            pa0 = *(const float4*)(Ag + k0 + BK);
            pa1 = *(const float4*)(Ag + k0 + BK + 4);
            pb0 = *(const float4*)(Bg + k0 + BK);
            pb1 = *(const float4*)(Bg + k0 + BK + 4);
        }

#pragma unroll
        for (int kk = 0; kk < BK; kk++) {
            float4 aL = *(const float4*)(&As[buf][kk][ty * 4]);
            float4 aH = *(const float4*)(&As[buf][kk][ty * 4 + 64]);
            float4 bL = *(const float4*)(&Bs[buf][kk][tx * 4]);
            float4 bH = *(const float4*)(&Bs[buf][kk][tx * 4 + 64]);
            float am[8] = {aL.x, aL.y, aL.z, aL.w, aH.x, aH.y, aH.z, aH.w};
            float bn[8] = {bL.x, bL.y, bL.z, bL.w, bH.x, bH.y, bH.z, bH.w};
#pragma unroll
            for (int i = 0; i < 8; i++)
#pragma unroll
                for (int j = 0; j < 8; j++)
                    acc[i][j] = fmaf(am[i], bn[j], acc[i][j]);
        }

        if (more) {
            int nb = buf ^ 1;
            As[nb][lc + 0][lr] = pa0.x; As[nb][lc + 1][lr] = pa0.y;
            As[nb][lc + 2][lr] = pa0.z; As[nb][lc + 3][lr] = pa0.w;
            As[nb][lc + 4][lr] = pa1.x; As[nb][lc + 5][lr] = pa1.y;
            As[nb][lc + 6][lr] = pa1.z; As[nb][lc + 7][lr] = pa1.w;
            Bs[nb][lc + 0][lr] = pb0.x; Bs[nb][lc + 1][lr] = pb0.y;
            Bs[nb][lc + 2][lr] = pb0.z; Bs[nb][lc + 3][lr] = pb0.w;
            Bs[nb][lc + 4][lr] = pb1.x; Bs[nb][lc + 5][lr] = pb1.y;
            Bs[nb][lc + 6][lr] = pb1.z; Bs[nb][lc + 7][lr] = pb1.w;
            __syncthreads();
            buf = nb;
        }
    }

    const int colL = nBase + tx * 4;
    const int colH = colL + 64;
    float4 bvL = *(const float4*)(bias + colL);
    float4 bvH = *(const float4*)(bias + colH);

#pragma unroll
    for (int hm = 0; hm < 2; hm++) {
#pragma unroll
        for (int i = 0; i < 4; i++) {
            int row = mBase + ty * 4 + i + hm * 64;
            int ii = hm * 4 + i;
            float4 oL, oH;
            oL.x = acc[ii][0] + bvL.x; oL.y = acc[ii][1] + bvL.y;
            oL.z = acc[ii][2] + bvL.z; oL.w = acc[ii][3] + bvL.w;
            oH.x = acc[ii][4] + bvH.x; oH.y = acc[ii][5] + bvH.y;
            oH.z = acc[ii][6] + bvH.z; oH.w = acc[ii][7] + bvH.w;
            *(float4*)(C + (size_t)row * N + colL) = oL;
            *(float4*)(C + (size_t)row * N + colH) = oH;
        }
    }
}

// ---------------------------------------------------------------------------
// Fused attention, flash-style, 128x128 tile.
// S phase: 16x16 threads, 8x8 micro-tile over [128q x 128k]  (4:1 FMA:smem).
// PV phase: tx = (txh, txd); txd (0..7) owns dims txd*8..+7 (64 = HD),
//           txh (0..1) owns key half txh*64..+63. 8q x 8d x 64k per thread
//           (4:1 FMA:smem). Halves summed at the end via shfl_xor(.,8)
//           (partner = lane^8, same warp). m/l identical across tx lanes, so
//           scaling commutes with the reduction.
// Mask: only kt==qt tile, (kg>>6)==(qg>>6) && kg>qg (CHUNK=64 inside 128 tile).
// ---------------------------------------------------------------------------
#define AQT 128
#define AKT 128
#define LDQK 132   // [d=64][q or k = 128+4]
#define LDV  68    // [k=128][d=64+4]
#define LDPS 132   // [q=128][k=128+4]

__global__ __launch_bounds__(256)
void attn_kernel(const float* __restrict__ Q, const float* __restrict__ K,
                 const float* __restrict__ V, const float* __restrict__ scale_p,
                 float* __restrict__ O)
{
    extern __shared__ float smem[];
    float (*Qs)[LDQK] = (float(*)[LDQK])(smem);                       // [64][132]
    float (*Ks)[LDQK] = (float(*)[LDQK])(smem + HD * LDQK);           // [64][132]
    float (*Vs)[LDV]  = (float(*)[LDV]) (smem + 2 * HD * LDQK);       // [128][68]
    float (*Ps)[LDPS] = (float(*)[LDPS])(smem + 2 * HD * LDQK + AKT * LDV); // [128][132]

    const int tid = threadIdx.x;
    const int tx  = tid & 15;
    const int ty  = tid >> 4;
    const int txd = tx & 7;        // output-dim group (PV)
    const int txh = tx >> 3;       // key half (PV)
    const int qt = blockIdx.x, h = blockIdx.y, b = blockIdx.z;
    const float scale = scale_p[0];

    // loader mapping: r = row 0..127, c = 32-float half of the 64-dim row
    const int r = tid >> 1;
    const int c = (tid & 1) * 32;

    // Load Q tile transposed (d-major), scale folded in
    {
        const float* Qb = Q + ((size_t)b * Tlen + qt * AQT + r) * EMB + h * HD + c;
#pragma unroll
        for (int j = 0; j < 8; j++) {
            float4 q4 = *(const float4*)(Qb + 4 * j);
            Qs[c + 4 * j + 0][r] = q4.x * scale;
            Qs[c + 4 * j + 1][r] = q4.y * scale;
            Qs[c + 4 * j + 2][r] = q4.z * scale;
            Qs[c + 4 * j + 3][r] = q4.w * scale;
        }
    }

    float m[8], l[8], o[8][8];
#pragma unroll
    for (int i = 0; i < 8; i++) {
        m[i] = -INFINITY; l[i] = 0.f;
#pragma unroll
        for (int j = 0; j < 8; j++) o[i][j] = 0.f;
    }

    for (int kt = 0; kt < Tlen / AKT; kt++) {
        __syncthreads();   // protect Ks/Vs/Ps reuse (and Qs on first iter)
        {
            const float* Kb = K + ((size_t)b * Tlen + kt * AKT + r) * EMB + h * HD + c;
            const float* Vb = V + ((size_t)b * Tlen + kt * AKT + r) * EMB + h * HD + c;
#pragma unroll
            for (int j = 0; j < 8; j++) {
                float4 k4 = *(const float4*)(Kb + 4 * j);
                Ks[c + 4 * j + 0][r] = k4.x;
                Ks[c + 4 * j + 1][r] = k4.y;
                Ks[c + 4 * j + 2][r] = k4.z;
                Ks[c + 4 * j + 3][r] = k4.w;
                *(float4*)&Vs[r][c + 4 * j] = *(const float4*)(Vb + 4 * j);
            }
        }
        __syncthreads();

        // ---- S = (Q*scale) . K^T : 8x8 register tile ----
        float s[8][8];
#pragma unroll
        for (int i = 0; i < 8; i++)
#pragma unroll
            for (int j = 0; j < 8; j++) s[i][j] = 0.f;

#pragma unroll 4
        for (int d = 0; d < HD; d++) {
            float4 qL = *(const float4*)&Qs[d][ty * 8];
            float4 qH = *(const float4*)&Qs[d][ty * 8 + 4];
            float4 kL = *(const float4*)&Ks[d][tx * 8];
            float4 kH = *(const float4*)&Ks[d][tx * 8 + 4];
            float qa[8] = {qL.x, qL.y, qL.z, qL.w, qH.x, qH.y, qH.z, qH.w};
            float kb[8] = {kL.x, kL.y, kL.z, kL.w, kH.x, kH.y, kH.z, kH.w};
#pragma unroll
            for (int i = 0; i < 8; i++)
#pragma unroll
                for (int j = 0; j < 8; j++)
                    s[i][j] = fmaf(qa[i], kb[j], s[i][j]);
        }

        if (kt == qt) {
#pragma unroll
            for (int i = 0; i < 8; i++) {
                int qg = ty * 8 + i;
#pragma unroll
                for (int j = 0; j < 8; j++) {
                    int kg = tx * 8 + j;
                    if ((kg >> 6) == (qg >> 6) && kg > qg) s[i][j] = -INFINITY;
                }
            }
        }

        // ---- online softmax: per-row stats reduced over the 16 tx lanes ----
#pragma unroll
        for (int i = 0; i < 8; i++) {
            float tm = fmaxf(fmaxf(fmaxf(s[i][0], s[i][1]), fmaxf(s[i][2], s[i][3])),
                             fmaxf(fmaxf(s[i][4], s[i][5]), fmaxf(s[i][6], s[i][7])));
            tm = fmaxf(tm, __shfl_xor_sync(0xffffffffu, tm, 1));
            tm = fmaxf(tm, __shfl_xor_sync(0xffffffffu, tm, 2));
            tm = fmaxf(tm, __shfl_xor_sync(0xffffffffu, tm, 4));
            tm = fmaxf(tm, __shfl_xor_sync(0xffffffffu, tm, 8));
            float mnew = fmaxf(m[i], tm);
            float corr = __expf(m[i] - mnew);   // 0 when m == -inf

            float p[8];
            float ts = 0.f;
#pragma unroll
            for (int j = 0; j < 8; j++) {
                p[j] = __expf(s[i][j] - mnew);
                ts += p[j];
            }
            ts += __shfl_xor_sync(0xffffffffu, ts, 1);
            ts += __shfl_xor_sync(0xffffffffu, ts, 2);
            ts += __shfl_xor_sync(0xffffffffu, ts, 4);
            ts += __shfl_xor_sync(0xffffffffu, ts, 8);
            l[i] = l[i] * corr + ts;
            m[i] = mnew;
#pragma unroll
            for (int j = 0; j < 8; j++) o[i][j] *= corr;
            *(float4*)&Ps[ty * 8 + i][tx * 8]     = make_float4(p[0], p[1], p[2], p[3]);
            *(float4*)&Ps[ty * 8 + i][tx * 8 + 4] = make_float4(p[4], p[5], p[6], p[7]);
        }
        __syncthreads();   // Ps complete before PV

        // ---- O += P . V : split-K. This thread: keys [txh*64, txh*64+64),
        //      dims [txd*8, txd*8+8). 4096 FMA / 1024 smem floats. ----
        const int kbeg = txh * 64;
#pragma unroll 2
        for (int kk = kbeg; kk < kbeg + 64; kk += 4) {
            float4 v0L = *(const float4*)&Vs[kk + 0][txd * 8];
            float4 v0H = *(const float4*)&Vs[kk + 0][txd * 8 + 4];
            float4 v1L = *(const float4*)&Vs[kk + 1][txd * 8];
            float4 v1H = *(const float4*)&Vs[kk + 1][txd * 8 + 4];
            float4 v2L = *(const float4*)&Vs[kk + 2][txd * 8];
            float4 v2H = *(const float4*)&Vs[kk + 2][txd * 8 + 4];
            float4 v3L = *(const float4*)&Vs[kk + 3][txd * 8];
            float4 v3H = *(const float4*)&Vs[kk + 3][txd * 8 + 4];
            float vb[4][8] = {
                {v0L.x, v0L.y, v0L.z, v0L.w, v0H.x, v0H.y, v0H.z, v0H.w},
                {v1L.x, v1L.y, v1L.z, v1L.w, v1H.x, v1H.y, v1H.z, v1H.w},
                {v2L.x, v2L.y, v2L.z, v2L.w, v2H.x, v2H.y, v2H.z, v2H.w},
                {v3L.x, v3L.y, v3L.z, v3L.w, v3H.x, v3H.y, v3H.z, v3H.w},
            };
#pragma unroll
            for (int i = 0; i < 8; i++) {
                float4 pr = *(const float4*)&Ps[ty * 8 + i][kk];
                float pa[4] = {pr.x, pr.y, pr.z, pr.w};
#pragma unroll
                for (int t = 0; t < 4; t++)
#pragma unroll
                    for (int j = 0; j < 8; j++)
                        o[i][j] = fmaf(pa[t], vb[t][j], o[i][j]);
            }
        }
    }

    // ---- combine key halves (partner lane = lane ^ 8, same warp) ----
#pragma unroll
    for (int i = 0; i < 8; i++)
#pragma unroll
        for (int j = 0; j < 8; j++)
            o[i][j] += __shfl_xor_sync(0xffffffffu, o[i][j], 8);

    // ---- finalize + store: txh=0 stores rows i=0..3, txh=1 rows i=4..7 ----
    {
        const int ibeg = txh * 4;
#pragma unroll
        for (int ii = 0; ii < 4; ii++) {
            int i = ibeg + ii;
            float inv = 1.f / l[i];
            float* Ob = O + ((size_t)b * Tlen + qt * AQT + ty * 8 + i) * EMB
                          + h * HD + txd * 8;
            *(float4*)Ob       = make_float4(o[i][0] * inv, o[i][1] * inv,
                                             o[i][2] * inv, o[i][3] * inv);
            *(float4*)(Ob + 4) = make_float4(o[i][4] * inv, o[i][5] * inv,
                                             o[i][6] * inv, o[i][7] * inv);
        }
    }
}

// ---------------------------------------------------------------------------
// Launch
// ---------------------------------------------------------------------------
extern "C" void kernel_launch(void* const* d_in, const int* in_sizes, int n_in,
                              void* d_out, int out_size)
{
    const float* x     = (const float*)d_in[0];
    const float* Wq    = (const float*)d_in[1];
    const float* bq    = (const float*)d_in[2];
    const float* Wk    = (const float*)d_in[3];
    const float* bk    = (const float*)d_in[4];
    const float* Wv    = (const float*)d_in[5];
    const float* bv    = (const float*)d_in[6];
    const float* Wo    = (const float*)d_in[7];
    const float* bo    = (const float*)d_in[8];
    const float* ascl  = (const float*)d_in[9];
    float* out = (float*)d_out;

    float *q, *k, *v, *attn;
    cudaGetSymbolAddress((void**)&q,    g_q);
    cudaGetSymbolAddress((void**)&k,    g_k);
    cudaGetSymbolAddress((void**)&v,    g_v);
    cudaGetSymbolAddress((void**)&attn, g_attn);

    const int M = MTOT, N = EMB, K = EMB;
    dim3 ggrid(N / BN, M / BM);   // (8, 64)
    dim3 gblk(256);

    gemm_nt_bias<<<ggrid, gblk>>>(x, Wq, bq, q, M, N, K);
    gemm_nt_bias<<<ggrid, gblk>>>(x, Wk, bk, k, M, N, K);
    gemm_nt_bias<<<ggrid, gblk>>>(x, Wv, bv, v, M, N, K);

    // smem: Qs + Ks + Vs + Ps = 169,984 bytes
    const int smem_bytes = (2 * HD * LDQK + AKT * LDV + AQT * LDPS) * (int)sizeof(float);
    cudaFuncSetAttribute(attn_kernel,
                         cudaFuncAttributeMaxDynamicSharedMemorySize, smem_bytes);

    dim3 agrid(Tlen / AQT, NHEADS, Bsz);  // (8, 16, 8)
    attn_kernel<<<agrid, 256, smem_bytes>>>(q, k, v, ascl, attn);

    gemm_nt_bias<<<ggrid, gblk>>>(attn, Wo, bo, out, M, N, K);
}

// round 9
// speedup vs baseline: 2.8714x; 1.0222x over previous
#include <cuda_runtime.h>
#include <math.h>

// Problem constants
#define Bsz    8
#define Tlen   1024
#define EMB    1024
#define NHEADS 16
#define HD     64
#define CHUNK  64

#define MTOT (Bsz * Tlen)          // 8192 rows

// ---------------------------------------------------------------------------
// Scratch (device globals — allocation-free per harness rules)
// ---------------------------------------------------------------------------
__device__ float g_q[MTOT * EMB];
__device__ float g_k[MTOT * EMB];
__device__ float g_v[MTOT * EMB];
__device__ float g_attn[MTOT * EMB];

// ---------------------------------------------------------------------------
// GEMM core: C[128,128] tile of A[M,K] * B[N,K]^T + bias, double-buffered.
// ---------------------------------------------------------------------------
#define BM 128
#define BN 128
#define BK 16
#define LDA (BM + 4)
#define LDB (BN + 4)
#define GK  1024   // K is always EMB

__device__ __forceinline__
void gemm_tile_body(const float* __restrict__ A, const float* __restrict__ B,
                    const float* __restrict__ bias, float* __restrict__ C,
                    int mBase, int nBase, int N)
{
    __shared__ float As[2][BK][LDA];
    __shared__ float Bs[2][BK][LDB];

    const int tid = threadIdx.x;
    const int tx = tid & 15;
    const int ty = tid >> 4;

    const int lr = tid >> 1;           // 0..127
    const int lc = (tid & 1) * 8;      // 0 or 8

    const float* Ag = A + (size_t)(mBase + lr) * GK + lc;
    const float* Bg = B + (size_t)(nBase + lr) * GK + lc;

    float acc[8][8];
#pragma unroll
    for (int i = 0; i < 8; i++)
#pragma unroll
        for (int j = 0; j < 8; j++) acc[i][j] = 0.f;

    {
        float4 a0 = *(const float4*)(Ag);
        float4 a1 = *(const float4*)(Ag + 4);
        float4 b0 = *(const float4*)(Bg);
        float4 b1 = *(const float4*)(Bg + 4);
        As[0][lc + 0][lr] = a0.x; As[0][lc + 1][lr] = a0.y;
        As[0][lc + 2][lr] = a0.z; As[0][lc + 3][lr] = a0.w;
        As[0][lc + 4][lr] = a1.x; As[0][lc + 5][lr] = a1.y;
        As[0][lc + 6][lr] = a1.z; As[0][lc + 7][lr] = a1.w;
        Bs[0][lc + 0][lr] = b0.x; Bs[0][lc + 1][lr] = b0.y;
        Bs[0][lc + 2][lr] = b0.z; Bs[0][lc + 3][lr] = b0.w;
        Bs[0][lc + 4][lr] = b1.x; Bs[0][lc + 5][lr] = b1.y;
        Bs[0][lc + 6][lr] = b1.z; Bs[0][lc + 7][lr] = b1.w;
    }
    __syncthreads();

    int buf = 0;
    for (int k0 = 0; k0 < GK; k0 += BK) {
        float4 pa0, pa1, pb0, pb1;
        const bool more = (k0 + BK) < GK;
        if (more) {
            pa0 = *(const float4*)(Ag + k0 + BK);
            pa1 = *(const float4*)(Ag + k0 + BK + 4);
            pb0 = *(const float4*)(Bg + k0 + BK);
            pb1 = *(const float4*)(Bg + k0 + BK + 4);
        }

#pragma unroll
        for (int kk = 0; kk < BK; kk++) {
            float4 aL = *(const float4*)(&As[buf][kk][ty * 4]);
            float4 aH = *(const float4*)(&As[buf][kk][ty * 4 + 64]);
            float4 bL = *(const float4*)(&Bs[buf][kk][tx * 4]);
            float4 bH = *(const float4*)(&Bs[buf][kk][tx * 4 + 64]);
            float am[8] = {aL.x, aL.y, aL.z, aL.w, aH.x, aH.y, aH.z, aH.w};
            float bn[8] = {bL.x, bL.y, bL.z, bL.w, bH.x, bH.y, bH.z, bH.w};
#pragma unroll
            for (int i = 0; i < 8; i++)
#pragma unroll
                for (int j = 0; j < 8; j++)
                    acc[i][j] = fmaf(am[i], bn[j], acc[i][j]);
        }

        if (more) {
            int nb = buf ^ 1;
            As[nb][lc + 0][lr] = pa0.x; As[nb][lc + 1][lr] = pa0.y;
            As[nb][lc + 2][lr] = pa0.z; As[nb][lc + 3][lr] = pa0.w;
            As[nb][lc + 4][lr] = pa1.x; As[nb][lc + 5][lr] = pa1.y;
            As[nb][lc + 6][lr] = pa1.z; As[nb][lc + 7][lr] = pa1.w;
            Bs[nb][lc + 0][lr] = pb0.x; Bs[nb][lc + 1][lr] = pb0.y;
            Bs[nb][lc + 2][lr] = pb0.z; Bs[nb][lc + 3][lr] = pb0.w;
            Bs[nb][lc + 4][lr] = pb1.x; Bs[nb][lc + 5][lr] = pb1.y;
            Bs[nb][lc + 6][lr] = pb1.z; Bs[nb][lc + 7][lr] = pb1.w;
            __syncthreads();
            buf = nb;
        }
    }

    const int colL = nBase + tx * 4;
    const int colH = colL + 64;
    float4 bvL = *(const float4*)(bias + colL);
    float4 bvH = *(const float4*)(bias + colH);

#pragma unroll
    for (int hm = 0; hm < 2; hm++) {
#pragma unroll
        for (int i = 0; i < 4; i++) {
            int row = mBase + ty * 4 + i + hm * 64;
            int ii = hm * 4 + i;
            float4 oL, oH;
            oL.x = acc[ii][0] + bvL.x; oL.y = acc[ii][1] + bvL.y;
            oL.z = acc[ii][2] + bvL.z; oL.w = acc[ii][3] + bvL.w;
            oH.x = acc[ii][4] + bvH.x; oH.y = acc[ii][5] + bvH.y;
            oH.z = acc[ii][6] + bvH.z; oH.w = acc[ii][7] + bvH.w;
            *(float4*)(C + (size_t)row * N + colL) = oL;
            *(float4*)(C + (size_t)row * N + colH) = oH;
        }
    }
}

// Fused QKV projection: grid.x = 24 (3 matrices x 8 n-tiles), grid.y = 64.
__global__ __launch_bounds__(256)
void gemm_qkv(const float* __restrict__ x,
              const float* __restrict__ Wq, const float* __restrict__ Wk,
              const float* __restrict__ Wv,
              const float* __restrict__ bq, const float* __restrict__ bk,
              const float* __restrict__ bv,
              float* __restrict__ q, float* __restrict__ k, float* __restrict__ v)
{
    const int sel = blockIdx.x >> 3;
    const int nb  = blockIdx.x & 7;
    const float* B    = (sel == 0) ? Wq : (sel == 1) ? Wk : Wv;
    const float* bias = (sel == 0) ? bq : (sel == 1) ? bk : bv;
    float* C          = (sel == 0) ? q  : (sel == 1) ? k  : v;
    gemm_tile_body(x, B, bias, C, blockIdx.y * BM, nb * BN, EMB);
}

// Single GEMM (output projection)
__global__ __launch_bounds__(256)
void gemm_nt_bias(const float* __restrict__ A, const float* __restrict__ B,
                  const float* __restrict__ bias, float* __restrict__ C)
{
    gemm_tile_body(A, B, bias, C, blockIdx.y * BM, blockIdx.x * BN, EMB);
}

// ---------------------------------------------------------------------------
// Fused attention, flash-style. 128q x 64k tile, 256 threads = 32 ty x 8 tx.
// S phase:  thread = 4q x 8k over full d=64  (micro 4x8).
// PV phase: thread = 4q x 8d over full k=64  (no cross-lane combine needed).
// Ps rows are produced AND consumed within one warp -> __syncwarp only.
// smem = 103.4 KB -> 2 CTAs/SM (16 warps). __launch_bounds__(256,2).
// Mask: key masked iff same 64-chunk as query and key>query. With AKT=64 the
// diagonal tile for row qr is kt == qt*2 + (qr>>6); inside it mask
// (tx*8+j) > (qr & 63).
// ---------------------------------------------------------------------------
#define AQT 128
#define AKT 64
#define LDQ 132   // Qs [d=64][q=128+4]
#define LDK 68    // Ks [d=64][k=64+4]
#define LDVV 68   // Vs [k=64][d=64+4]
#define LDP 68    // Ps [q=128][k=64+4]

__global__ __launch_bounds__(256, 2)
void attn_kernel(const float* __restrict__ Q, const float* __restrict__ K,
                 const float* __restrict__ V, const float* __restrict__ scale_p,
                 float* __restrict__ O)
{
    extern __shared__ float smem[];
    float (*Qs)[LDQ]  = (float(*)[LDQ]) (smem);                              // [64][132]
    float (*Ks)[LDK]  = (float(*)[LDK]) (smem + HD * LDQ);                   // [64][68]
    float (*Vs)[LDVV] = (float(*)[LDVV])(smem + HD * LDQ + HD * LDK);        // [64][68]
    float (*Ps)[LDP]  = (float(*)[LDP]) (smem + HD * LDQ + HD * (LDK + LDVV)); // [128][68]

    const int tid = threadIdx.x;
    const int tx  = tid & 7;        // 8 key-groups (S) / 8 dim-groups (PV)
    const int ty  = tid >> 3;       // 32 q-groups of 4 rows
    const int qt = blockIdx.x, h = blockIdx.y, b = blockIdx.z;
    const float scale = scale_p[0];

    // ---- load Q tile transposed (d-major), scale folded in ----
    {
        const int r = tid >> 1;            // 0..127
        const int c = (tid & 1) * 32;      // 0 or 32
        const float* Qb = Q + ((size_t)b * Tlen + qt * AQT + r) * EMB + h * HD + c;
#pragma unroll
        for (int j = 0; j < 8; j++) {
            float4 q4 = *(const float4*)(Qb + 4 * j);
            Qs[c + 4 * j + 0][r] = q4.x * scale;
            Qs[c + 4 * j + 1][r] = q4.y * scale;
            Qs[c + 4 * j + 2][r] = q4.z * scale;
            Qs[c + 4 * j + 3][r] = q4.w * scale;
        }
    }

    float m[4], l[4], o[4][8];
#pragma unroll
    for (int i = 0; i < 4; i++) {
        m[i] = -INFINITY; l[i] = 0.f;
#pragma unroll
        for (int j = 0; j < 8; j++) o[i][j] = 0.f;
    }

    const int r2 = tid >> 2;          // 0..63
    const int c2 = (tid & 3) * 16;    // 0,16,32,48

    for (int kt = 0; kt < Tlen / AKT; kt++) {
        __syncthreads();   // K/V (+Qs first iter) safe to (over)write
        {
            const float* Kb = K + ((size_t)b * Tlen + kt * AKT + r2) * EMB + h * HD + c2;
            const float* Vb = V + ((size_t)b * Tlen + kt * AKT + r2) * EMB + h * HD + c2;
#pragma unroll
            for (int j = 0; j < 4; j++) {
                float4 k4 = *(const float4*)(Kb + 4 * j);
                Ks[c2 + 4 * j + 0][r2] = k4.x;
                Ks[c2 + 4 * j + 1][r2] = k4.y;
                Ks[c2 + 4 * j + 2][r2] = k4.z;
                Ks[c2 + 4 * j + 3][r2] = k4.w;
                *(float4*)&Vs[r2][c2 + 4 * j] = *(const float4*)(Vb + 4 * j);
            }
        }
        __syncthreads();

        // ---- S = (Q*scale) . K^T : 4x8 register tile over d=64 ----
        float s[4][8];
#pragma unroll
        for (int i = 0; i < 4; i++)
#pragma unroll
            for (int j = 0; j < 8; j++) s[i][j] = 0.f;

#pragma unroll 4
        for (int d = 0; d < HD; d++) {
            float4 qv = *(const float4*)&Qs[d][ty * 4];
            float4 kL = *(const float4*)&Ks[d][tx * 8];
            float4 kH = *(const float4*)&Ks[d][tx * 8 + 4];
            float qa[4] = {qv.x, qv.y, qv.z, qv.w};
            float kb8[8] = {kL.x, kL.y, kL.z, kL.w, kH.x, kH.y, kH.z, kH.w};
#pragma unroll
            for (int i = 0; i < 4; i++)
#pragma unroll
                for (int j = 0; j < 8; j++)
                    s[i][j] = fmaf(qa[i], kb8[j], s[i][j]);
        }

        // ---- mask (diagonal chunk only) ----
#pragma unroll
        for (int i = 0; i < 4; i++) {
            const int qr = ty * 4 + i;
            if (kt == qt * 2 + (qr >> 6)) {
                const int rel = qr & 63;
#pragma unroll
                for (int j = 0; j < 8; j++)
                    if (tx * 8 + j > rel) s[i][j] = -INFINITY;
            }
        }

        // ---- online softmax: reduce across the 8 tx lanes (bits 0..2) ----
#pragma unroll
        for (int i = 0; i < 4; i++) {
            float tm = fmaxf(fmaxf(fmaxf(s[i][0], s[i][1]), fmaxf(s[i][2], s[i][3])),
                             fmaxf(fmaxf(s[i][4], s[i][5]), fmaxf(s[i][6], s[i][7])));
            tm = fmaxf(tm, __shfl_xor_sync(0xffffffffu, tm, 1));
            tm = fmaxf(tm, __shfl_xor_sync(0xffffffffu, tm, 2));
            tm = fmaxf(tm, __shfl_xor_sync(0xffffffffu, tm, 4));
            float mnew = fmaxf(m[i], tm);
            float corr = __expf(m[i] - mnew);   // 0 when m == -inf

            float p[8];
            float ts = 0.f;
#pragma unroll
            for (int j = 0; j < 8; j++) {
                p[j] = __expf(s[i][j] - mnew);
                ts += p[j];
            }
            ts += __shfl_xor_sync(0xffffffffu, ts, 1);
            ts += __shfl_xor_sync(0xffffffffu, ts, 2);
            ts += __shfl_xor_sync(0xffffffffu, ts, 4);
            l[i] = l[i] * corr + ts;
            m[i] = mnew;
#pragma unroll
            for (int j = 0; j < 8; j++) o[i][j] *= corr;
            *(float4*)&Ps[ty * 4 + i][tx * 8]     = make_float4(p[0], p[1], p[2], p[3]);
            *(float4*)&Ps[ty * 4 + i][tx * 8 + 4] = make_float4(p[4], p[5], p[6], p[7]);
        }
        __syncwarp();   // Ps rows are warp-private: producer lanes == consumer lanes' warp

        // ---- O += P . V : rows ty*4.., dims tx*8.., all 64 keys ----
#pragma unroll 2
        for (int kk = 0; kk < AKT; kk += 4) {
            float4 v0L = *(const float4*)&Vs[kk + 0][tx * 8];
            float4 v0H = *(const float4*)&Vs[kk + 0][tx * 8 + 4];
            float4 v1L = *(const float4*)&Vs[kk + 1][tx * 8];
            float4 v1H = *(const float4*)&Vs[kk + 1][tx * 8 + 4];
            float4 v2L = *(const float4*)&Vs[kk + 2][tx * 8];
            float4 v2H = *(const float4*)&Vs[kk + 2][tx * 8 + 4];
            float4 v3L = *(const float4*)&Vs[kk + 3][tx * 8];
            float4 v3H = *(const float4*)&Vs[kk + 3][tx * 8 + 4];
            float vb[4][8] = {
                {v0L.x, v0L.y, v0L.z, v0L.w, v0H.x, v0H.y, v0H.z, v0H.w},
                {v1L.x, v1L.y, v1L.z, v1L.w, v1H.x, v1H.y, v1H.z, v1H.w},
                {v2L.x, v2L.y, v2L.z, v2L.w, v2H.x, v2H.y, v2H.z, v2H.w},
                {v3L.x, v3L.y, v3L.z, v3L.w, v3H.x, v3H.y, v3H.z, v3H.w},
            };
#pragma unroll
            for (int i = 0; i < 4; i++) {
                float4 pr = *(const float4*)&Ps[ty * 4 + i][kk];
                float pa[4] = {pr.x, pr.y, pr.z, pr.w};
#pragma unroll
                for (int t = 0; t < 4; t++)
#pragma unroll
                    for (int j = 0; j < 8; j++)
                        o[i][j] = fmaf(pa[t], vb[t][j], o[i][j]);
            }
        }
    }

    // ---- finalize + store (each thread owns its 4 rows x 8 dims) ----
#pragma unroll
    for (int i = 0; i < 4; i++) {
        float inv = 1.f / l[i];
        float* Ob = O + ((size_t)b * Tlen + qt * AQT + ty * 4 + i) * EMB
                      + h * HD + tx * 8;
        *(float4*)Ob       = make_float4(o[i][0] * inv, o[i][1] * inv,
                                         o[i][2] * inv, o[i][3] * inv);
        *(float4*)(Ob + 4) = make_float4(o[i][4] * inv, o[i][5] * inv,
                                         o[i][6] * inv, o[i][7] * inv);
    }
}

// ---------------------------------------------------------------------------
// Launch
// ---------------------------------------------------------------------------
extern "C" void kernel_launch(void* const* d_in, const int* in_sizes, int n_in,
                              void* d_out, int out_size)
{
    const float* x     = (const float*)d_in[0];
    const float* Wq    = (const float*)d_in[1];
    const float* bq    = (const float*)d_in[2];
    const float* Wk    = (const float*)d_in[3];
    const float* bk    = (const float*)d_in[4];
    const float* Wv    = (const float*)d_in[5];
    const float* bv    = (const float*)d_in[6];
    const float* Wo    = (const float*)d_in[7];
    const float* bo    = (const float*)d_in[8];
    const float* ascl  = (const float*)d_in[9];
    float* out = (float*)d_out;

    float *q, *k, *v, *attn;
    cudaGetSymbolAddress((void**)&q,    g_q);
    cudaGetSymbolAddress((void**)&k,    g_k);
    cudaGetSymbolAddress((void**)&v,    g_v);
    cudaGetSymbolAddress((void**)&attn, g_attn);

    // Fused QKV projections: 24 x 64 CTAs
    dim3 qkvGrid(24, MTOT / BM);
    gemm_qkv<<<qkvGrid, 256>>>(x, Wq, Wk, Wv, bq, bk, bv, q, k, v);

    // Attention
    const int smem_bytes = (HD * LDQ + HD * LDK + HD * LDVV + AQT * LDP)
                           * (int)sizeof(float);   // 103,424 B
    cudaFuncSetAttribute(attn_kernel,
                         cudaFuncAttributeMaxDynamicSharedMemorySize, smem_bytes);
    dim3 agrid(Tlen / AQT, NHEADS, Bsz);  // (8, 16, 8)
    attn_kernel<<<agrid, 256, smem_bytes>>>(q, k, v, ascl, attn);

    // Output projection
    dim3 ggrid(EMB / BN, MTOT / BM);   // (8, 64)
    gemm_nt_bias<<<ggrid, 256>>>(attn, Wo, bo, out);
}